// round 7
// baseline (speedup 1.0000x reference)
#include <cuda_runtime.h>

#define F 16384
#define NJ 22
#define STRIDE (NJ*3)   // 66 floats per frame
#define NBINS 25
#define INV4PI 0.07957747154594767f
#define PIO2 1.5707963267948966f
#define TF 64           // frames per transpose tile

// ---------------- device scratch (no allocs allowed) ----------------
__device__ float g_m1T[STRIDE * F];   // [j*3+c][frame]
__device__ float g_m2T[STRIDE * F];
__device__ unsigned char g_flag[F];
__device__ float g_gli[NBINS * F];    // [bin][frame]  (frame-contiguous)

__constant__ int c_pathj[5][5] = {
    {2, 5, 8, 11, 0},
    {1, 4, 7, 10, 0},
    {3, 6, 9, 12, 15},
    {14, 17, 19, 21, 0},
    {13, 16, 18, 20, 0}
};
__constant__ int c_plen[5] = {4, 4, 5, 4, 4};

// ---------------- small vec helpers ----------------
struct V3 { float x, y, z; };

__device__ __forceinline__ V3 vsub(V3 a, V3 b) { return {a.x - b.x, a.y - b.y, a.z - b.z}; }
__device__ __forceinline__ V3 vcrs(V3 a, V3 b) {
    return {fmaf(a.y, b.z, -a.z * b.y),
            fmaf(a.z, b.x, -a.x * b.z),
            fmaf(a.x, b.y, -a.y * b.x)};
}
__device__ __forceinline__ float vdot(V3 a, V3 b) {
    return fmaf(a.x, b.x, fmaf(a.y, b.y, a.z * b.z));
}
// _safe_normalize semantics: zero vector -> zero scale (downstream dot -> 0)
__device__ __forceinline__ float invnorm(V3 v) {
    float n2 = vdot(v, v);
    return (n2 > 0.f) ? rsqrtf(n2) : 0.f;
}

// Branch-free asin (A&S 4.4.45). For |d| >= 1 the s>0 guard yields exactly
// +-pi/2, identical to clipping first.
__device__ __forceinline__ float fast_asin(float d) {
    float ax = fabsf(d);
    float p = fmaf(ax, -0.0012624911f, 0.0066700901f);
    p = fmaf(ax, p, -0.0170881256f);
    p = fmaf(ax, p,  0.0308918810f);
    p = fmaf(ax, p, -0.0501743046f);
    p = fmaf(ax, p,  0.0889789874f);
    p = fmaf(ax, p, -0.2145988016f);
    p = fmaf(ax, p,  1.5707963050f);
    float s = 1.0f - ax;
    float r = (s > 0.f) ? (s * rsqrtf(s)) * p : 0.f;   // sqrt(s)*p via MUFU.RSQ
    return copysignf(PIO2 - r, d);
}

__device__ __forceinline__ float edge_asin(V3 a, float ra, V3 b, float rb) {
    return fast_asin(vdot(a, b) * ra * rb);
}

// ---------------- kernel 1: AoS->SoA transpose (one motion per block) ------
__global__ void __launch_bounds__(256) transpose_kernel(
        const float* __restrict__ m1, const float* __restrict__ m2) {
    __shared__ float tile[TF * 67];   // padded stride 67 -> conflict-free
    int f0 = blockIdx.x * TF;
    const float* in = blockIdx.y ? m2 : m1;
    float* out = blockIdx.y ? g_m2T : g_m1T;

    for (int idx = threadIdx.x; idx < TF * STRIDE; idx += 256) {
        int fl = idx / STRIDE, sl = idx % STRIDE;
        tile[fl * 67 + sl] = in[f0 * STRIDE + idx];
    }
    __syncthreads();
    for (int idx = threadIdx.x; idx < STRIDE * TF; idx += 256) {
        int slot = idx >> 6;        // idx / TF
        int fl = idx & (TF - 1);
        out[slot * F + f0 + fl] = tile[fl * 67 + slot];
    }
}

// ---------------- kernel 2: per-frame XZ bbox overlap flag ----------------
__global__ void mask_kernel() {
    int f = blockIdx.x * blockDim.x + threadIdx.x;
    if (f >= F) return;
    float x1n = 1e30f, x1x = -1e30f, z1n = 1e30f, z1x = -1e30f;
    float x2n = 1e30f, x2x = -1e30f, z2n = 1e30f, z2x = -1e30f;
#pragma unroll
    for (int j = 0; j < NJ; j++) {
        float x1 = g_m1T[(j * 3 + 0) * F + f];
        float z1 = g_m1T[(j * 3 + 2) * F + f];
        float x2 = g_m2T[(j * 3 + 0) * F + f];
        float z2 = g_m2T[(j * 3 + 2) * F + f];
        x1n = fminf(x1n, x1); x1x = fmaxf(x1x, x1);
        z1n = fminf(z1n, z1); z1x = fmaxf(z1x, z1);
        x2n = fminf(x2n, x2); x2x = fmaxf(x2x, x2);
        z2n = fminf(z2n, z2); z2x = fmaxf(z2x, z2);
    }
    bool ovx = !((x1x < x2n) || (x2x < x1n));
    bool ovz = !((z1x < z2n) || (z2x < z1n));
    g_flag[f] = (unsigned char)(ovx && ovz);
}

// ---------------- GLI pair sum (batched preload, cross-product form) -------
template <int NA, int NB>
__device__ __forceinline__ float gli_body(int f, int a, int b) {
    V3 P1[NA], P2[NB];
#pragma unroll
    for (int k = 0; k < NA; k++) {
        int j = c_pathj[a][k];
        P1[k].x = g_m1T[(j * 3 + 0) * F + f];
        P1[k].y = g_m1T[(j * 3 + 1) * F + f];
        P1[k].z = g_m1T[(j * 3 + 2) * F + f];
    }
#pragma unroll
    for (int k = 0; k < NB; k++) {
        int j = c_pathj[b][k];
        P2[k].x = g_m2T[(j * 3 + 0) * F + f];
        P2[k].y = g_m2T[(j * 3 + 1) * F + f];
        P2[k].z = g_m2T[(j * 3 + 2) * F + f];
    }

    float acc = 0.f;
#pragma unroll
    for (int i = 0; i < NA - 1; i++) {
        V3 s1 = P1[i], e1 = P1[i + 1];
        V3 r12 = vsub(e1, s1);
#pragma unroll
        for (int j = 0; j < NB - 1; j++) {
            V3 s2 = P2[j], e2 = P2[j + 1];
            V3 r13 = vsub(s2, s1);
            V3 r14 = vsub(e2, s1);
            V3 r23 = vsub(r13, r12);   // s2 - e1
            V3 r24 = vsub(r14, r12);   // e2 - e1
            V3 r34 = vsub(r14, r13);   // e2 - s2
            V3 f0 = vcrs(r13, r14);
            V3 f1 = vcrs(r14, r24);
            V3 f2 = vcrs(r24, r23);
            V3 f3 = vcrs(r23, r13);
            float r0 = invnorm(f0), r1 = invnorm(f1);
            float r2 = invnorm(f2), r3 = invnorm(f3);
            float t = edge_asin(f0, r0, f1, r1)
                    + edge_asin(f1, r1, f2, r2)
                    + edge_asin(f2, r2, f3, r3)
                    + edge_asin(f3, r3, f0, r0);
            float sg = vdot(vcrs(r34, r12), r13);
            acc += (sg > 0.f) ? t : -t;
        }
    }
    return acc;
}

// ---------------- kernel 3: per-(bin, frame) GLI, masked ----------------
__global__ void __launch_bounds__(256) gli_kernel() {
    int f = blockIdx.x * blockDim.x + threadIdx.x;
    int bin = blockIdx.y;                 // uniform per block -> no divergence
    int a = bin / 5, b = bin % 5;
    int na = c_plen[a], nb = c_plen[b];

    float acc;
    int key = ((na == 5) ? 2 : 0) | ((nb == 5) ? 1 : 0);
    switch (key) {                         // block-uniform branch
        case 0: acc = gli_body<4, 4>(f, a, b); break;
        case 1: acc = gli_body<4, 5>(f, a, b); break;
        case 2: acc = gli_body<5, 4>(f, a, b); break;
        default: acc = gli_body<5, 5>(f, a, b); break;
    }

    // window mask: flag[f] | flag[f-1] | flag[f+1]
    bool m = g_flag[f];
    if (f > 0)     m = m || g_flag[f - 1];
    if (f < F - 1) m = m || g_flag[f + 1];
    g_gli[bin * F + f] = acc * INV4PI * (m ? 1.f : 0.f);   // coalesced store
}

// ---------------- kernel 4: max |delta| over bins (coalesced, full chip) ---
__global__ void vel_kernel(float* __restrict__ out) {
    int t = blockIdx.x * blockDim.x + threadIdx.x;
    if (t >= F - 1) return;
    float best = 0.f;
#pragma unroll
    for (int bin = 0; bin < NBINS; bin++) {
        float a = g_gli[bin * F + t];
        float b = g_gli[bin * F + t + 1];
        best = fmaxf(best, fabsf(b - a));
    }
    out[t] = best;
}

// ---------------- launcher ----------------
extern "C" void kernel_launch(void* const* d_in, const int* in_sizes, int n_in,
                              void* d_out, int out_size) {
    const float* m1 = (const float*)d_in[0];
    const float* m2 = (const float*)d_in[1];
    float* out = (float*)d_out;

    transpose_kernel<<<dim3(F / TF, 2), 256>>>(m1, m2);
    mask_kernel<<<F / 256, 256>>>();
    gli_kernel<<<dim3(F / 256, NBINS), 256>>>();
    vel_kernel<<<(F + 127) / 128, 128>>>(out);
}

// round 8
// speedup vs baseline: 1.1294x; 1.1294x over previous
#include <cuda_runtime.h>

#define F 16384
#define NJ 22
#define STRIDE (NJ*3)   // 66 floats per frame
#define NBINS 25
#define INV4PI 0.07957747154594767f
#define PIO2 1.5707963267948966f
#define TF 64           // frames per transpose tile

// ---------------- device scratch (no allocs allowed) ----------------
__device__ float g_m1T[STRIDE * F];   // [j*3+c][frame]
__device__ float g_m2T[STRIDE * F];
__device__ unsigned char g_flag[F];
__device__ float g_gli[NBINS * F];    // [bin][frame]  (frame-contiguous)

__constant__ int c_pathj[5][5] = {
    {2, 5, 8, 11, 0},
    {1, 4, 7, 10, 0},
    {3, 6, 9, 12, 15},
    {14, 17, 19, 21, 0},
    {13, 16, 18, 20, 0}
};
__constant__ int c_plen[5] = {4, 4, 5, 4, 4};

// ---------------- small vec helpers ----------------
struct V3 { float x, y, z; };

__device__ __forceinline__ V3 vsub(V3 a, V3 b) { return {a.x - b.x, a.y - b.y, a.z - b.z}; }
__device__ __forceinline__ V3 vcrs(V3 a, V3 b) {
    return {fmaf(a.y, b.z, -a.z * b.y),
            fmaf(a.z, b.x, -a.x * b.z),
            fmaf(a.x, b.y, -a.y * b.x)};
}
__device__ __forceinline__ float vdot(V3 a, V3 b) {
    return fmaf(a.x, b.x, fmaf(a.y, b.y, a.z * b.z));
}
// _safe_normalize semantics: zero vector -> zero scale (downstream dot -> 0)
__device__ __forceinline__ float invnorm(V3 v) {
    float n2 = vdot(v, v);
    return (n2 > 0.f) ? rsqrtf(n2) : 0.f;
}

// Branch-free asin (A&S 4.4.45). For |d| >= 1 the s>0 guard yields exactly
// +-pi/2, identical to clipping first.
__device__ __forceinline__ float fast_asin(float d) {
    float ax = fabsf(d);
    float p = fmaf(ax, -0.0012624911f, 0.0066700901f);
    p = fmaf(ax, p, -0.0170881256f);
    p = fmaf(ax, p,  0.0308918810f);
    p = fmaf(ax, p, -0.0501743046f);
    p = fmaf(ax, p,  0.0889789874f);
    p = fmaf(ax, p, -0.2145988016f);
    p = fmaf(ax, p,  1.5707963050f);
    float s = 1.0f - ax;
    float r = (s > 0.f) ? (s * rsqrtf(s)) * p : 0.f;   // sqrt(s)*p via MUFU.RSQ
    return copysignf(PIO2 - r, d);
}

// ---------------- kernel 1: transpose (both motions) + window flag --------
__global__ void __launch_bounds__(256) transpose_mask_kernel(
        const float* __restrict__ m1, const float* __restrict__ m2) {
    __shared__ float t1[TF * 67];   // padded stride 67 -> conflict-free
    __shared__ float t2[TF * 67];
    int f0 = blockIdx.x * TF;

    for (int idx = threadIdx.x; idx < TF * STRIDE; idx += 256) {
        int fl = idx / STRIDE, sl = idx % STRIDE;
        t1[fl * 67 + sl] = m1[f0 * STRIDE + idx];
        t2[fl * 67 + sl] = m2[f0 * STRIDE + idx];
    }
    __syncthreads();
    for (int idx = threadIdx.x; idx < STRIDE * TF; idx += 256) {
        int slot = idx >> 6;        // idx / TF
        int fl = idx & (TF - 1);
        g_m1T[slot * F + f0 + fl] = t1[fl * 67 + slot];
        g_m2T[slot * F + f0 + fl] = t2[fl * 67 + slot];
    }
    // XZ bbox overlap flags for this block's TF frames (from smem)
    if (threadIdx.x < TF) {
        int fl = threadIdx.x;
        float x1n = 1e30f, x1x = -1e30f, z1n = 1e30f, z1x = -1e30f;
        float x2n = 1e30f, x2x = -1e30f, z2n = 1e30f, z2x = -1e30f;
#pragma unroll
        for (int j = 0; j < NJ; j++) {
            float x1 = t1[fl * 67 + j * 3 + 0];
            float z1 = t1[fl * 67 + j * 3 + 2];
            float x2 = t2[fl * 67 + j * 3 + 0];
            float z2 = t2[fl * 67 + j * 3 + 2];
            x1n = fminf(x1n, x1); x1x = fmaxf(x1x, x1);
            z1n = fminf(z1n, z1); z1x = fmaxf(z1x, z1);
            x2n = fminf(x2n, x2); x2x = fmaxf(x2x, x2);
            z2n = fminf(z2n, z2); z2x = fmaxf(z2x, z2);
        }
        bool ovx = !((x1x < x2n) || (x2x < x1n));
        bool ovz = !((z1x < z2n) || (z2x < z1n));
        g_flag[f0 + fl] = (unsigned char)(ovx && ovz);
    }
}

// ---------------- GLI pair sum: batched preload + j-direction face reuse ---
// Across j -> j+1:  r13' = r14, r23' = r24, f3' = cross(r23',r13')
//                 = cross(r24, r14) = -f1.  asin is odd, so the two terms
// involving f3' flip sign. Exact algebra, no approximation.
template <int NA, int NB>
__device__ __forceinline__ float gli_body(int f, int a, int b) {
    V3 P1[NA], P2[NB];
#pragma unroll
    for (int k = 0; k < NA; k++) {
        int j = c_pathj[a][k];
        P1[k].x = g_m1T[(j * 3 + 0) * F + f];
        P1[k].y = g_m1T[(j * 3 + 1) * F + f];
        P1[k].z = g_m1T[(j * 3 + 2) * F + f];
    }
#pragma unroll
    for (int k = 0; k < NB; k++) {
        int j = c_pathj[b][k];
        P2[k].x = g_m2T[(j * 3 + 0) * F + f];
        P2[k].y = g_m2T[(j * 3 + 1) * F + f];
        P2[k].z = g_m2T[(j * 3 + 2) * F + f];
    }

    float acc = 0.f;
#pragma unroll
    for (int i = 0; i < NA - 1; i++) {
        V3 s1 = P1[i], e1 = P1[i + 1];
        V3 r12 = vsub(e1, s1);

        // ---- j = 0: full evaluation ----
        V3 r13 = vsub(P2[0], s1);
        V3 r14 = vsub(P2[1], s1);
        V3 r23 = vsub(r13, r12);
        V3 r24 = vsub(r14, r12);
        V3 f0v = vcrs(r13, r14);
        V3 f1v = vcrs(r14, r24);
        V3 f2v = vcrs(r24, r23);
        V3 f3v = vcrs(r23, r13);
        float r0 = invnorm(f0v), r1 = invnorm(f1v);
        float r2 = invnorm(f2v), r3 = invnorm(f3v);
        {
            float t = fast_asin(vdot(f0v, f1v) * (r0 * r1))
                    + fast_asin(vdot(f1v, f2v) * (r1 * r2))
                    + fast_asin(vdot(f2v, f3v) * (r2 * r3))
                    + fast_asin(vdot(f3v, f0v) * (r3 * r0));
            V3 r34 = vsub(r14, r13);
            float sg = vdot(vcrs(r34, r12), r13);
            acc += (sg > 0.f) ? t : -t;
        }

        // carried state: f1v/r1 (previous f1), r14/r24 (become r13'/r23')
#pragma unroll
        for (int j = 1; j < NB - 1; j++) {
            V3 p13 = r14;              // r13' = previous r14
            V3 p23 = r24;              // r23' = previous r24
            r14 = vsub(P2[j + 1], s1);
            r24 = vsub(r14, r12);
            V3 nf0 = vcrs(p13, r14);
            V3 nf1 = vcrs(r14, r24);
            V3 nf2 = vcrs(r24, p23);
            float n0 = invnorm(nf0), n1 = invnorm(nf1), n2 = invnorm(nf2);
            // f3' = -f1(prev) with norm r1 -> last two asin terms negate
            float t = fast_asin(vdot(nf0, nf1) * (n0 * n1))
                    + fast_asin(vdot(nf1, nf2) * (n1 * n2))
                    - fast_asin(vdot(nf2, f1v) * (n2 * r1))
                    - fast_asin(vdot(f1v, nf0) * (r1 * n0));
            V3 r34 = vsub(r14, p13);
            float sg = vdot(vcrs(r34, r12), p13);
            acc += (sg > 0.f) ? t : -t;
            f1v = nf1; r1 = n1;
        }
    }
    return acc;
}

// ---------------- kernel 2: per-(bin, frame) GLI, masked ----------------
__global__ void __launch_bounds__(256) gli_kernel() {
    int f = blockIdx.x * blockDim.x + threadIdx.x;
    int bin = blockIdx.y;                 // uniform per block -> no divergence
    int a = bin / 5, b = bin % 5;
    int na = c_plen[a], nb = c_plen[b];

    float acc;
    int key = ((na == 5) ? 2 : 0) | ((nb == 5) ? 1 : 0);
    switch (key) {                         // block-uniform branch
        case 0: acc = gli_body<4, 4>(f, a, b); break;
        case 1: acc = gli_body<4, 5>(f, a, b); break;
        case 2: acc = gli_body<5, 4>(f, a, b); break;
        default: acc = gli_body<5, 5>(f, a, b); break;
    }

    // window mask: flag[f] | flag[f-1] | flag[f+1]
    bool m = g_flag[f];
    if (f > 0)     m = m || g_flag[f - 1];
    if (f < F - 1) m = m || g_flag[f + 1];
    g_gli[bin * F + f] = acc * INV4PI * (m ? 1.f : 0.f);   // coalesced store
}

// ---------------- kernel 3: max |delta| over bins (parallel + reduce) ------
// block = (64 t, 4 bin-groups); groups cover 7/6/6/6 bins; smem max-reduce.
__global__ void vel_kernel(float* __restrict__ out) {
    __shared__ float red[4][64];
    int t = blockIdx.x * 64 + threadIdx.x;
    int g = threadIdx.y;
    int b0 = (g == 0) ? 0 : 7 + (g - 1) * 6;
    int b1 = (g == 0) ? 7 : b0 + 6;
    float best = 0.f;
    if (t < F - 1) {
        for (int bin = b0; bin < b1; bin++) {
            float a0 = g_gli[bin * F + t];
            float a1 = g_gli[bin * F + t + 1];
            best = fmaxf(best, fabsf(a1 - a0));
        }
    }
    red[g][threadIdx.x] = best;
    __syncthreads();
    if (g == 0 && t < F - 1) {
        best = fmaxf(fmaxf(red[0][threadIdx.x], red[1][threadIdx.x]),
                     fmaxf(red[2][threadIdx.x], red[3][threadIdx.x]));
        out[t] = best;
    }
}

// ---------------- launcher ----------------
extern "C" void kernel_launch(void* const* d_in, const int* in_sizes, int n_in,
                              void* d_out, int out_size) {
    const float* m1 = (const float*)d_in[0];
    const float* m2 = (const float*)d_in[1];
    float* out = (float*)d_out;

    transpose_mask_kernel<<<F / TF, 256>>>(m1, m2);
    gli_kernel<<<dim3(F / 256, NBINS), 256>>>();
    vel_kernel<<<F / 64, dim3(64, 4)>>>(out);
}

// round 10
// speedup vs baseline: 1.1779x; 1.0429x over previous
#include <cuda_runtime.h>

#define F 16384
#define NJ 22
#define STRIDE (NJ*3)   // 66 floats per frame
#define NBINS 25
#define INV4PI 0.07957747154594767f
#define PIO2 1.5707963267948966f
#define TF 32           // frames per transpose tile (512 blocks -> 3.5/SM)

// ---------------- device scratch (no allocs allowed) ----------------
__device__ float g_m1T[STRIDE * F];   // [j*3+c][frame]
__device__ float g_m2T[STRIDE * F];
__device__ unsigned char g_flag[F];
__device__ float g_gli[NBINS * F];    // [bin][frame]  (frame-contiguous)

__constant__ int c_pathj[5][5] = {
    {2, 5, 8, 11, 0},
    {1, 4, 7, 10, 0},
    {3, 6, 9, 12, 15},
    {14, 17, 19, 21, 0},
    {13, 16, 18, 20, 0}
};
__constant__ int c_plen[5] = {4, 4, 5, 4, 4};

// ---------------- small vec helpers ----------------
struct V3 { float x, y, z; };

__device__ __forceinline__ V3 vsub(V3 a, V3 b) { return {a.x - b.x, a.y - b.y, a.z - b.z}; }
__device__ __forceinline__ V3 vcrs(V3 a, V3 b) {
    return {fmaf(a.y, b.z, -a.z * b.y),
            fmaf(a.z, b.x, -a.x * b.z),
            fmaf(a.x, b.y, -a.y * b.x)};
}
__device__ __forceinline__ float vdot(V3 a, V3 b) {
    return fmaf(a.x, b.x, fmaf(a.y, b.y, a.z * b.z));
}
// _safe_normalize semantics: zero vector -> zero scale (downstream dot -> 0)
__device__ __forceinline__ float invnorm(V3 v) {
    float n2 = vdot(v, v);
    return (n2 > 0.f) ? rsqrtf(n2) : 0.f;
}

// Branch-free asin (A&S 4.4.45). For |d| >= 1 the s>0 guard yields exactly
// +-pi/2, identical to clipping first.
__device__ __forceinline__ float fast_asin(float d) {
    float ax = fabsf(d);
    float p = fmaf(ax, -0.0012624911f, 0.0066700901f);
    p = fmaf(ax, p, -0.0170881256f);
    p = fmaf(ax, p,  0.0308918810f);
    p = fmaf(ax, p, -0.0501743046f);
    p = fmaf(ax, p,  0.0889789874f);
    p = fmaf(ax, p, -0.2145988016f);
    p = fmaf(ax, p,  1.5707963050f);
    float s = 1.0f - ax;
    float r = (s > 0.f) ? (s * rsqrtf(s)) * p : 0.f;   // sqrt(s)*p via MUFU.RSQ
    return copysignf(PIO2 - r, d);
}

// ---------------- kernel 1: transpose (both motions) + window flag --------
__global__ void __launch_bounds__(256) transpose_mask_kernel(
        const float* __restrict__ m1, const float* __restrict__ m2) {
    __shared__ float t1[TF * 67];   // padded stride 67 -> conflict-free
    __shared__ float t2[TF * 67];
    int f0 = blockIdx.x * TF;

    for (int idx = threadIdx.x; idx < TF * STRIDE; idx += 256) {
        int fl = idx / STRIDE, sl = idx % STRIDE;
        t1[fl * 67 + sl] = m1[f0 * STRIDE + idx];
        t2[fl * 67 + sl] = m2[f0 * STRIDE + idx];
    }
    __syncthreads();
    for (int idx = threadIdx.x; idx < STRIDE * TF; idx += 256) {
        int slot = idx >> 5;        // idx / TF
        int fl = idx & (TF - 1);
        g_m1T[slot * F + f0 + fl] = t1[fl * 67 + slot];
        g_m2T[slot * F + f0 + fl] = t2[fl * 67 + slot];
    }
    // XZ bbox overlap flags for this block's TF frames (from smem)
    if (threadIdx.x < TF) {
        int fl = threadIdx.x;
        float x1n = 1e30f, x1x = -1e30f, z1n = 1e30f, z1x = -1e30f;
        float x2n = 1e30f, x2x = -1e30f, z2n = 1e30f, z2x = -1e30f;
#pragma unroll
        for (int j = 0; j < NJ; j++) {
            float x1 = t1[fl * 67 + j * 3 + 0];
            float z1 = t1[fl * 67 + j * 3 + 2];
            float x2 = t2[fl * 67 + j * 3 + 0];
            float z2 = t2[fl * 67 + j * 3 + 2];
            x1n = fminf(x1n, x1); x1x = fmaxf(x1x, x1);
            z1n = fminf(z1n, z1); z1x = fmaxf(z1x, z1);
            x2n = fminf(x2n, x2); x2x = fmaxf(x2x, x2);
            z2n = fminf(z2n, z2); z2x = fmaxf(z2x, z2);
        }
        bool ovx = !((x1x < x2n) || (x2x < x1n));
        bool ovz = !((z1x < z2n) || (z2x < z1n));
        g_flag[f0 + fl] = (unsigned char)(ovx && ovz);
    }
}

// ---------------- GLI pair sum: batched preload + j-direction face reuse ---
// Across j -> j+1:  r13' = r14, r23' = r24, f3' = cross(r23',r13')
//                 = cross(r24, r14) = -f1.  asin is odd, so the two terms
// involving f3' flip sign. Exact algebra, no approximation.
template <int NA, int NB>
__device__ __forceinline__ float gli_body(int f, int a, int b) {
    V3 P1[NA], P2[NB];
#pragma unroll
    for (int k = 0; k < NA; k++) {
        int j = c_pathj[a][k];
        P1[k].x = g_m1T[(j * 3 + 0) * F + f];
        P1[k].y = g_m1T[(j * 3 + 1) * F + f];
        P1[k].z = g_m1T[(j * 3 + 2) * F + f];
    }
#pragma unroll
    for (int k = 0; k < NB; k++) {
        int j = c_pathj[b][k];
        P2[k].x = g_m2T[(j * 3 + 0) * F + f];
        P2[k].y = g_m2T[(j * 3 + 1) * F + f];
        P2[k].z = g_m2T[(j * 3 + 2) * F + f];
    }

    float acc = 0.f;
#pragma unroll
    for (int i = 0; i < NA - 1; i++) {
        V3 s1 = P1[i], e1 = P1[i + 1];
        V3 r12 = vsub(e1, s1);

        // ---- j = 0: full evaluation ----
        V3 r13 = vsub(P2[0], s1);
        V3 r14 = vsub(P2[1], s1);
        V3 r23 = vsub(r13, r12);
        V3 r24 = vsub(r14, r12);
        V3 f0v = vcrs(r13, r14);
        V3 f1v = vcrs(r14, r24);
        V3 f2v = vcrs(r24, r23);
        V3 f3v = vcrs(r23, r13);
        float r0 = invnorm(f0v), r1 = invnorm(f1v);
        float r2 = invnorm(f2v), r3 = invnorm(f3v);
        {
            float t = fast_asin(vdot(f0v, f1v) * (r0 * r1))
                    + fast_asin(vdot(f1v, f2v) * (r1 * r2))
                    + fast_asin(vdot(f2v, f3v) * (r2 * r3))
                    + fast_asin(vdot(f3v, f0v) * (r3 * r0));
            V3 r34 = vsub(r14, r13);
            float sg = vdot(vcrs(r34, r12), r13);
            acc += (sg > 0.f) ? t : -t;
        }

        // carried state: f1v/r1 (previous f1), r14/r24 (become r13'/r23')
#pragma unroll
        for (int j = 1; j < NB - 1; j++) {
            V3 p13 = r14;              // r13' = previous r14
            V3 p23 = r24;              // r23' = previous r24
            r14 = vsub(P2[j + 1], s1);
            r24 = vsub(r14, r12);
            V3 nf0 = vcrs(p13, r14);
            V3 nf1 = vcrs(r14, r24);
            V3 nf2 = vcrs(r24, p23);
            float n0 = invnorm(nf0), n1 = invnorm(nf1), n2 = invnorm(nf2);
            // f3' = -f1(prev) with norm r1 -> last two asin terms negate
            float t = fast_asin(vdot(nf0, nf1) * (n0 * n1))
                    + fast_asin(vdot(nf1, nf2) * (n1 * n2))
                    - fast_asin(vdot(nf2, f1v) * (n2 * r1))
                    - fast_asin(vdot(f1v, nf0) * (r1 * n0));
            V3 r34 = vsub(r14, p13);
            float sg = vdot(vcrs(r34, r12), p13);
            acc += (sg > 0.f) ? t : -t;
            f1v = nf1; r1 = n1;
        }
    }
    return acc;
}

// ---------------- kernel 2: per-(bin, frame) GLI, masked ----------------
__global__ void __launch_bounds__(256) gli_kernel() {
    int f = blockIdx.x * blockDim.x + threadIdx.x;
    int bin = blockIdx.y;                 // uniform per block -> no divergence
    int a = bin / 5, b = bin % 5;
    int na = c_plen[a], nb = c_plen[b];

    float acc;
    int key = ((na == 5) ? 2 : 0) | ((nb == 5) ? 1 : 0);
    switch (key) {                         // block-uniform branch
        case 0: acc = gli_body<4, 4>(f, a, b); break;
        case 1: acc = gli_body<4, 5>(f, a, b); break;
        case 2: acc = gli_body<5, 4>(f, a, b); break;
        default: acc = gli_body<5, 5>(f, a, b); break;
    }

    // window mask: flag[f] | flag[f-1] | flag[f+1]
    bool m = g_flag[f];
    if (f > 0)     m = m || g_flag[f - 1];
    if (f < F - 1) m = m || g_flag[f + 1];
    g_gli[bin * F + f] = acc * INV4PI * (m ? 1.f : 0.f);   // coalesced store
}

// ---------------- kernel 3: max |delta| over bins (parallel + reduce) ------
// block = (64 t, 4 bin-groups); groups cover 7/6/6/6 bins; smem max-reduce.
__global__ void vel_kernel(float* __restrict__ out) {
    __shared__ float red[4][64];
    int t = blockIdx.x * 64 + threadIdx.x;
    int g = threadIdx.y;
    int b0 = (g == 0) ? 0 : 7 + (g - 1) * 6;
    int b1 = (g == 0) ? 7 : b0 + 6;
    float best = 0.f;
    if (t < F - 1) {
        for (int bin = b0; bin < b1; bin++) {
            float a0 = g_gli[bin * F + t];
            float a1 = g_gli[bin * F + t + 1];
            best = fmaxf(best, fabsf(a1 - a0));
        }
    }
    red[g][threadIdx.x] = best;
    __syncthreads();
    if (g == 0 && t < F - 1) {
        best = fmaxf(fmaxf(red[0][threadIdx.x], red[1][threadIdx.x]),
                     fmaxf(red[2][threadIdx.x], red[3][threadIdx.x]));
        out[t] = best;
    }
}

// ---------------- launcher ----------------
extern "C" void kernel_launch(void* const* d_in, const int* in_sizes, int n_in,
                              void* d_out, int out_size) {
    const float* m1 = (const float*)d_in[0];
    const float* m2 = (const float*)d_in[1];
    float* out = (float*)d_out;

    transpose_mask_kernel<<<F / TF, 256>>>(m1, m2);
    gli_kernel<<<dim3(F / 256, NBINS), 256>>>();
    vel_kernel<<<F / 64, dim3(64, 4)>>>(out);
}

// round 11
// speedup vs baseline: 1.1861x; 1.0069x over previous
#include <cuda_runtime.h>

#define F 16384
#define NJ 22
#define STRIDE (NJ*3)   // 66 floats per frame
#define NBINS 25
#define INV4PI 0.07957747154594767f
#define PIO2 1.5707963267948966f
#define TF 16           // frames per transpose tile (1024 blocks -> ~7/SM)

// ---------------- device scratch (no allocs allowed) ----------------
__device__ float g_m1T[STRIDE * F];   // [j*3+c][frame]
__device__ float g_m2T[STRIDE * F];
__device__ unsigned char g_flag[F];
__device__ float g_gli[NBINS * F];    // [bin][frame]  (frame-contiguous)

__constant__ int c_pathj[5][5] = {
    {2, 5, 8, 11, 0},
    {1, 4, 7, 10, 0},
    {3, 6, 9, 12, 15},
    {14, 17, 19, 21, 0},
    {13, 16, 18, 20, 0}
};
__constant__ int c_plen[5] = {4, 4, 5, 4, 4};

// ---------------- small vec helpers ----------------
struct V3 { float x, y, z; };

__device__ __forceinline__ V3 vsub(V3 a, V3 b) { return {a.x - b.x, a.y - b.y, a.z - b.z}; }
__device__ __forceinline__ V3 vcrs(V3 a, V3 b) {
    return {fmaf(a.y, b.z, -a.z * b.y),
            fmaf(a.z, b.x, -a.x * b.z),
            fmaf(a.x, b.y, -a.y * b.x)};
}
__device__ __forceinline__ float vdot(V3 a, V3 b) {
    return fmaf(a.x, b.x, fmaf(a.y, b.y, a.z * b.z));
}
// _safe_normalize semantics: zero vector -> zero scale (downstream dot -> 0)
__device__ __forceinline__ float invnorm(V3 v) {
    float n2 = vdot(v, v);
    return (n2 > 0.f) ? rsqrtf(n2) : 0.f;
}

// Branch-free asin (A&S 4.4.45). For |d| >= 1 the s>0 guard yields exactly
// +-pi/2, identical to clipping first.
__device__ __forceinline__ float fast_asin(float d) {
    float ax = fabsf(d);
    float p = fmaf(ax, -0.0012624911f, 0.0066700901f);
    p = fmaf(ax, p, -0.0170881256f);
    p = fmaf(ax, p,  0.0308918810f);
    p = fmaf(ax, p, -0.0501743046f);
    p = fmaf(ax, p,  0.0889789874f);
    p = fmaf(ax, p, -0.2145988016f);
    p = fmaf(ax, p,  1.5707963050f);
    float s = 1.0f - ax;
    float r = (s > 0.f) ? (s * rsqrtf(s)) * p : 0.f;   // sqrt(s)*p via MUFU.RSQ
    return copysignf(PIO2 - r, d);
}

// ---------------- kernel 1: transpose (both motions) + window flag --------
__global__ void __launch_bounds__(256) transpose_mask_kernel(
        const float* __restrict__ m1, const float* __restrict__ m2) {
    __shared__ float t1[TF * 67];   // padded stride 67 -> conflict-free
    __shared__ float t2[TF * 67];
    int f0 = blockIdx.x * TF;

    for (int idx = threadIdx.x; idx < TF * STRIDE; idx += 256) {
        int fl = idx / STRIDE, sl = idx % STRIDE;
        t1[fl * 67 + sl] = m1[f0 * STRIDE + idx];
        t2[fl * 67 + sl] = m2[f0 * STRIDE + idx];
    }
    __syncthreads();
    for (int idx = threadIdx.x; idx < STRIDE * TF; idx += 256) {
        int slot = idx >> 4;        // idx / TF
        int fl = idx & (TF - 1);
        g_m1T[slot * F + f0 + fl] = t1[fl * 67 + slot];
        g_m2T[slot * F + f0 + fl] = t2[fl * 67 + slot];
    }
    // XZ bbox overlap flags for this block's TF frames (from smem)
    if (threadIdx.x < TF) {
        int fl = threadIdx.x;
        float x1n = 1e30f, x1x = -1e30f, z1n = 1e30f, z1x = -1e30f;
        float x2n = 1e30f, x2x = -1e30f, z2n = 1e30f, z2x = -1e30f;
#pragma unroll
        for (int j = 0; j < NJ; j++) {
            float x1 = t1[fl * 67 + j * 3 + 0];
            float z1 = t1[fl * 67 + j * 3 + 2];
            float x2 = t2[fl * 67 + j * 3 + 0];
            float z2 = t2[fl * 67 + j * 3 + 2];
            x1n = fminf(x1n, x1); x1x = fmaxf(x1x, x1);
            z1n = fminf(z1n, z1); z1x = fmaxf(z1x, z1);
            x2n = fminf(x2n, x2); x2x = fmaxf(x2x, x2);
            z2n = fminf(z2n, z2); z2x = fmaxf(z2x, z2);
        }
        bool ovx = !((x1x < x2n) || (x2x < x1n));
        bool ovz = !((z1x < z2n) || (z2x < z1n));
        g_flag[f0 + fl] = (unsigned char)(ovx && ovz);
    }
}

// ---------------- GLI pair sum: j-reuse AND i-reuse of faces ---------------
// j -> j+1:  f3' = cross(r23',r13') = cross(r24,r14) = -f1   (R8 win)
// i -> i+1:  r13' = r23, r14' = r24, so f0' = cross(r23,r24) = -f2(prev row)
// asin is odd, so each reused face flips the sign of its two asin terms.
// Exact algebra, no approximation. F2s/R2s carry prev-row f2 per column.
template <int NA, int NB>
__device__ __forceinline__ float gli_body(int f, int a, int b) {
    V3 P1[NA], P2[NB];
#pragma unroll
    for (int k = 0; k < NA; k++) {
        int j = c_pathj[a][k];
        P1[k].x = g_m1T[(j * 3 + 0) * F + f];
        P1[k].y = g_m1T[(j * 3 + 1) * F + f];
        P1[k].z = g_m1T[(j * 3 + 2) * F + f];
    }
#pragma unroll
    for (int k = 0; k < NB; k++) {
        int j = c_pathj[b][k];
        P2[k].x = g_m2T[(j * 3 + 0) * F + f];
        P2[k].y = g_m2T[(j * 3 + 1) * F + f];
        P2[k].z = g_m2T[(j * 3 + 2) * F + f];
    }

    V3 F2s[NB - 1];
    float R2s[NB - 1];
    float acc = 0.f;
#pragma unroll
    for (int i = 0; i < NA - 1; i++) {
        V3 s1 = P1[i], e1 = P1[i + 1];
        V3 r12 = vsub(e1, s1);

        // ---- j = 0 ----
        V3 r13 = vsub(P2[0], s1);
        V3 r14 = vsub(P2[1], s1);
        V3 r23 = vsub(r13, r12);
        V3 r24 = vsub(r14, r12);
        V3 f1v = vcrs(r14, r24);
        V3 f2v = vcrs(r24, r23);
        V3 f3v = vcrs(r23, r13);
        float n1 = invnorm(f1v), n2 = invnorm(f2v), n3 = invnorm(f3v);
        V3 f0v; float n0, s0;
        if (i == 0) { f0v = vcrs(r13, r14); n0 = invnorm(f0v); s0 = 1.f; }
        else        { f0v = F2s[0];         n0 = R2s[0];       s0 = -1.f; }
        {
            float t = s0 * fast_asin(vdot(f0v, f1v) * (n0 * n1))
                    +      fast_asin(vdot(f1v, f2v) * (n1 * n2))
                    +      fast_asin(vdot(f2v, f3v) * (n2 * n3))
                    + s0 * fast_asin(vdot(f3v, f0v) * (n3 * n0));
            V3 r34 = vsub(r14, r13);
            float sg = vdot(vcrs(r34, r12), r13);
            acc += (sg > 0.f) ? t : -t;
        }
        F2s[0] = f2v; R2s[0] = n2;
        V3 f1p = f1v; float n1p = n1;

        // ---- j >= 1: reuse f3 = -f1p (j-dir) and f0 = -F2s[j] (i-dir) ----
#pragma unroll
        for (int j = 1; j < NB - 1; j++) {
            V3 p13 = r14;              // r13' = previous r14
            V3 p23 = r24;              // r23' = previous r24
            r14 = vsub(P2[j + 1], s1);
            r24 = vsub(r14, r12);
            V3 nf1 = vcrs(r14, r24);
            V3 nf2 = vcrs(r24, p23);
            float m1 = invnorm(nf1), m2 = invnorm(nf2);
            V3 g0; float m0, t0;
            if (i == 0) { g0 = vcrs(p13, r14); m0 = invnorm(g0); t0 = 1.f; }
            else        { g0 = F2s[j];         m0 = R2s[j];      t0 = -1.f; }
            float t = t0 * fast_asin(vdot(g0, nf1) * (m0 * m1))
                    +      fast_asin(vdot(nf1, nf2) * (m1 * m2))
                    -      fast_asin(vdot(nf2, f1p) * (m2 * n1p))
                    - t0 * fast_asin(vdot(f1p, g0) * (n1p * m0));
            V3 r34 = vsub(r14, p13);
            float sg = vdot(vcrs(r34, r12), p13);
            acc += (sg > 0.f) ? t : -t;
            F2s[j] = nf2; R2s[j] = m2;
            f1p = nf1; n1p = m1;
        }
    }
    return acc;
}

// ---------------- kernel 2: per-(bin, frame) GLI, masked ----------------
__global__ void __launch_bounds__(256) gli_kernel() {
    int f = blockIdx.x * blockDim.x + threadIdx.x;
    int bin = blockIdx.y;                 // uniform per block -> no divergence
    int a = bin / 5, b = bin % 5;
    int na = c_plen[a], nb = c_plen[b];

    float acc;
    int key = ((na == 5) ? 2 : 0) | ((nb == 5) ? 1 : 0);
    switch (key) {                         // block-uniform branch
        case 0: acc = gli_body<4, 4>(f, a, b); break;
        case 1: acc = gli_body<4, 5>(f, a, b); break;
        case 2: acc = gli_body<5, 4>(f, a, b); break;
        default: acc = gli_body<5, 5>(f, a, b); break;
    }

    // window mask: flag[f] | flag[f-1] | flag[f+1]
    bool m = g_flag[f];
    if (f > 0)     m = m || g_flag[f - 1];
    if (f < F - 1) m = m || g_flag[f + 1];
    g_gli[bin * F + f] = acc * INV4PI * (m ? 1.f : 0.f);   // coalesced store
}

// ---------------- kernel 3: max |delta| over bins (parallel + reduce) ------
// block = (64 t, 4 bin-groups); groups cover 7/6/6/6 bins; smem max-reduce.
__global__ void vel_kernel(float* __restrict__ out) {
    __shared__ float red[4][64];
    int t = blockIdx.x * 64 + threadIdx.x;
    int g = threadIdx.y;
    int b0 = (g == 0) ? 0 : 7 + (g - 1) * 6;
    int b1 = (g == 0) ? 7 : b0 + 6;
    float best = 0.f;
    if (t < F - 1) {
        for (int bin = b0; bin < b1; bin++) {
            float a0 = g_gli[bin * F + t];
            float a1 = g_gli[bin * F + t + 1];
            best = fmaxf(best, fabsf(a1 - a0));
        }
    }
    red[g][threadIdx.x] = best;
    __syncthreads();
    if (g == 0 && t < F - 1) {
        best = fmaxf(fmaxf(red[0][threadIdx.x], red[1][threadIdx.x]),
                     fmaxf(red[2][threadIdx.x], red[3][threadIdx.x]));
        out[t] = best;
    }
}

// ---------------- launcher ----------------
extern "C" void kernel_launch(void* const* d_in, const int* in_sizes, int n_in,
                              void* d_out, int out_size) {
    const float* m1 = (const float*)d_in[0];
    const float* m2 = (const float*)d_in[1];
    float* out = (float*)d_out;

    transpose_mask_kernel<<<F / TF, 256>>>(m1, m2);
    gli_kernel<<<dim3(F / 256, NBINS), 256>>>();
    vel_kernel<<<F / 64, dim3(64, 4)>>>(out);
}

// round 12
// speedup vs baseline: 1.2468x; 1.0511x over previous
#include <cuda_runtime.h>

#define F 16384
#define NJ 22
#define STRIDE (NJ*3)   // 66 floats per frame
#define NBINS 25
#define INV4PI 0.07957747154594767f
#define PIO2 1.5707963267948966f
#define TF 16           // frames per transpose tile (1024 blocks -> ~7/SM)

// ---------------- device scratch (no allocs allowed) ----------------
__device__ float g_m1T[STRIDE * F];   // [j*3+c][frame]
__device__ float g_m2T[STRIDE * F];
__device__ unsigned char g_flag[F];
__device__ float g_gli[NBINS * F];    // [bin][frame]  (frame-contiguous)

__constant__ int c_pathj[5][5] = {
    {2, 5, 8, 11, 0},
    {1, 4, 7, 10, 0},
    {3, 6, 9, 12, 15},
    {14, 17, 19, 21, 0},
    {13, 16, 18, 20, 0}
};
__constant__ int c_plen[5] = {4, 4, 5, 4, 4};

// ---------------- small vec helpers ----------------
struct V3 { float x, y, z; };

__device__ __forceinline__ V3 vsub(V3 a, V3 b) { return {a.x - b.x, a.y - b.y, a.z - b.z}; }
__device__ __forceinline__ V3 vcrs(V3 a, V3 b) {
    return {fmaf(a.y, b.z, -a.z * b.y),
            fmaf(a.z, b.x, -a.x * b.z),
            fmaf(a.x, b.y, -a.y * b.x)};
}
__device__ __forceinline__ float vdot(V3 a, V3 b) {
    return fmaf(a.x, b.x, fmaf(a.y, b.y, a.z * b.z));
}
// _safe_normalize semantics: zero vector -> zero scale (downstream dot -> 0)
__device__ __forceinline__ float invnorm(V3 v) {
    float n2 = vdot(v, v);
    return (n2 > 0.f) ? rsqrtf(n2) : 0.f;
}

// Branch-free asin (A&S 4.4.45). For |d| >= 1 the s>0 guard yields exactly
// +-pi/2, identical to clipping first.
__device__ __forceinline__ float fast_asin(float d) {
    float ax = fabsf(d);
    float p = fmaf(ax, -0.0012624911f, 0.0066700901f);
    p = fmaf(ax, p, -0.0170881256f);
    p = fmaf(ax, p,  0.0308918810f);
    p = fmaf(ax, p, -0.0501743046f);
    p = fmaf(ax, p,  0.0889789874f);
    p = fmaf(ax, p, -0.2145988016f);
    p = fmaf(ax, p,  1.5707963050f);
    float s = 1.0f - ax;
    float r = (s > 0.f) ? (s * rsqrtf(s)) * p : 0.f;   // sqrt(s)*p via MUFU.RSQ
    return copysignf(PIO2 - r, d);
}

// ---------------- kernel 1: transpose (both motions) + window flag --------
__global__ void __launch_bounds__(256) transpose_mask_kernel(
        const float* __restrict__ m1, const float* __restrict__ m2) {
    __shared__ float t1[TF * 67];   // padded stride 67 -> conflict-free
    __shared__ float t2[TF * 67];
    int f0 = blockIdx.x * TF;

    for (int idx = threadIdx.x; idx < TF * STRIDE; idx += 256) {
        int fl = idx / STRIDE, sl = idx % STRIDE;
        t1[fl * 67 + sl] = m1[f0 * STRIDE + idx];
        t2[fl * 67 + sl] = m2[f0 * STRIDE + idx];
    }
    __syncthreads();
    for (int idx = threadIdx.x; idx < STRIDE * TF; idx += 256) {
        int slot = idx >> 4;        // idx / TF
        int fl = idx & (TF - 1);
        g_m1T[slot * F + f0 + fl] = t1[fl * 67 + slot];
        g_m2T[slot * F + f0 + fl] = t2[fl * 67 + slot];
    }
    // XZ bbox overlap flags for this block's TF frames (from smem)
    if (threadIdx.x < TF) {
        int fl = threadIdx.x;
        float x1n = 1e30f, x1x = -1e30f, z1n = 1e30f, z1x = -1e30f;
        float x2n = 1e30f, x2x = -1e30f, z2n = 1e30f, z2x = -1e30f;
#pragma unroll
        for (int j = 0; j < NJ; j++) {
            float x1 = t1[fl * 67 + j * 3 + 0];
            float z1 = t1[fl * 67 + j * 3 + 2];
            float x2 = t2[fl * 67 + j * 3 + 0];
            float z2 = t2[fl * 67 + j * 3 + 2];
            x1n = fminf(x1n, x1); x1x = fmaxf(x1x, x1);
            z1n = fminf(z1n, z1); z1x = fmaxf(z1x, z1);
            x2n = fminf(x2n, x2); x2x = fmaxf(x2x, x2);
            z2n = fminf(z2n, z2); z2x = fmaxf(z2x, z2);
        }
        bool ovx = !((x1x < x2n) || (x2x < x1n));
        bool ovz = !((z1x < z2n) || (z2x < z1n));
        g_flag[f0 + fl] = (unsigned char)(ovx && ovz);
    }
}

// ---------------- one i-row of the GLI pair sum (j-reuse inside) -----------
// Across j -> j+1:  f3' = cross(r23',r13') = cross(r24,r14) = -f1.
// asin is odd -> the two f3' terms flip sign. Exact algebra.
template <int NB>
__device__ __forceinline__ float gli_row(int f, int a, int b, int i) {
    V3 P2[NB];
#pragma unroll
    for (int k = 0; k < NB; k++) {
        int j = c_pathj[b][k];
        P2[k].x = g_m2T[(j * 3 + 0) * F + f];
        P2[k].y = g_m2T[(j * 3 + 1) * F + f];
        P2[k].z = g_m2T[(j * 3 + 2) * F + f];
    }
    V3 s1, e1;
    {
        int j0 = c_pathj[a][i];
        int j1 = c_pathj[a][i + 1];
        s1.x = g_m1T[(j0 * 3 + 0) * F + f];
        s1.y = g_m1T[(j0 * 3 + 1) * F + f];
        s1.z = g_m1T[(j0 * 3 + 2) * F + f];
        e1.x = g_m1T[(j1 * 3 + 0) * F + f];
        e1.y = g_m1T[(j1 * 3 + 1) * F + f];
        e1.z = g_m1T[(j1 * 3 + 2) * F + f];
    }
    V3 r12 = vsub(e1, s1);

    float acc = 0.f;
    // ---- j = 0: full evaluation ----
    V3 r13 = vsub(P2[0], s1);
    V3 r14 = vsub(P2[1], s1);
    V3 r23 = vsub(r13, r12);
    V3 r24 = vsub(r14, r12);
    V3 f0v = vcrs(r13, r14);
    V3 f1v = vcrs(r14, r24);
    V3 f2v = vcrs(r24, r23);
    V3 f3v = vcrs(r23, r13);
    float r0 = invnorm(f0v), r1 = invnorm(f1v);
    float r2 = invnorm(f2v), r3 = invnorm(f3v);
    {
        float t = fast_asin(vdot(f0v, f1v) * (r0 * r1))
                + fast_asin(vdot(f1v, f2v) * (r1 * r2))
                + fast_asin(vdot(f2v, f3v) * (r2 * r3))
                + fast_asin(vdot(f3v, f0v) * (r3 * r0));
        V3 r34 = vsub(r14, r13);
        float sg = vdot(vcrs(r34, r12), r13);
        acc += (sg > 0.f) ? t : -t;
    }

    // carried state: f1v/r1 (previous f1), r14/r24 (become r13'/r23')
#pragma unroll
    for (int j = 1; j < NB - 1; j++) {
        V3 p13 = r14;              // r13' = previous r14
        V3 p23 = r24;              // r23' = previous r24
        r14 = vsub(P2[j + 1], s1);
        r24 = vsub(r14, r12);
        V3 nf0 = vcrs(p13, r14);
        V3 nf1 = vcrs(r14, r24);
        V3 nf2 = vcrs(r24, p23);
        float n0 = invnorm(nf0), n1 = invnorm(nf1), n2 = invnorm(nf2);
        // f3' = -f1(prev) with norm r1 -> last two asin terms negate
        float t = fast_asin(vdot(nf0, nf1) * (n0 * n1))
                + fast_asin(vdot(nf1, nf2) * (n1 * n2))
                - fast_asin(vdot(nf2, f1v) * (n2 * r1))
                - fast_asin(vdot(f1v, nf0) * (r1 * n0));
        V3 r34 = vsub(r14, p13);
        float sg = vdot(vcrs(r34, r12), p13);
        acc += (sg > 0.f) ? t : -t;
        f1v = nf1; r1 = n1;
    }
    return acc;
}

// ---------------- kernel 2: (frame x bin x i-row) GLI, masked --------------
// block = (64 frames, 4 rows); y is warp-uniform -> no divergence.
__global__ void __launch_bounds__(256) gli_kernel() {
    int f = blockIdx.x * 64 + threadIdx.x;
    int bin = blockIdx.y;
    int a = bin / 5, b = bin % 5;
    int na = c_plen[a], nb = c_plen[b];
    int i = threadIdx.y;

    float part = 0.f;
    if (i < na - 1) {
        if (nb == 5) part = gli_row<5>(f, a, b, i);   // block-uniform branch
        else         part = gli_row<4>(f, a, b, i);
    }

    __shared__ float red[4][64];
    red[threadIdx.y][threadIdx.x] = part;
    __syncthreads();
    if (threadIdx.y == 0) {
        float acc = red[0][threadIdx.x] + red[1][threadIdx.x]
                  + red[2][threadIdx.x] + red[3][threadIdx.x];
        // window mask: flag[f] | flag[f-1] | flag[f+1]
        bool m = g_flag[f];
        if (f > 0)     m = m || g_flag[f - 1];
        if (f < F - 1) m = m || g_flag[f + 1];
        g_gli[bin * F + f] = acc * INV4PI * (m ? 1.f : 0.f);  // coalesced
    }
}

// ---------------- kernel 3: max |delta| over bins (parallel + reduce) ------
// block = (64 t, 4 bin-groups); groups cover 7/6/6/6 bins; smem max-reduce.
__global__ void vel_kernel(float* __restrict__ out) {
    __shared__ float red[4][64];
    int t = blockIdx.x * 64 + threadIdx.x;
    int g = threadIdx.y;
    int b0 = (g == 0) ? 0 : 7 + (g - 1) * 6;
    int b1 = (g == 0) ? 7 : b0 + 6;
    float best = 0.f;
    if (t < F - 1) {
        for (int bin = b0; bin < b1; bin++) {
            float a0 = g_gli[bin * F + t];
            float a1 = g_gli[bin * F + t + 1];
            best = fmaxf(best, fabsf(a1 - a0));
        }
    }
    red[g][threadIdx.x] = best;
    __syncthreads();
    if (g == 0 && t < F - 1) {
        best = fmaxf(fmaxf(red[0][threadIdx.x], red[1][threadIdx.x]),
                     fmaxf(red[2][threadIdx.x], red[3][threadIdx.x]));
        out[t] = best;
    }
}

// ---------------- launcher ----------------
extern "C" void kernel_launch(void* const* d_in, const int* in_sizes, int n_in,
                              void* d_out, int out_size) {
    const float* m1 = (const float*)d_in[0];
    const float* m2 = (const float*)d_in[1];
    float* out = (float*)d_out;

    transpose_mask_kernel<<<F / TF, 256>>>(m1, m2);
    gli_kernel<<<dim3(F / 64, NBINS), dim3(64, 4)>>>();
    vel_kernel<<<F / 64, dim3(64, 4)>>>(out);
}